// round 2
// baseline (speedup 1.0000x reference)
#include <cuda_runtime.h>

#define TOKENS 32768
#define DIN    1024
#define DOUT   1024
#define RANK   16
#define SCALE1 0.5f   // 8/16
#define SCALE2 1.0f   // 16/16

// Scratch for the folded effective weight (no cudaMalloc allowed).
__device__ float g_Weff[DOUT * DIN];

// W_eff[o][i] = W[o][i] + SCALE1 * sum_r B1[o][r]*A1[r][i] + SCALE2 * sum_r B2[o][r]*A2[r][i]
__global__ __launch_bounds__(256)
void build_weff_kernel(const float* __restrict__ W,
                       const float* __restrict__ A1, const float* __restrict__ B1,
                       const float* __restrict__ A2, const float* __restrict__ B2) {
    int idx = blockIdx.x * blockDim.x + threadIdx.x;   // 0 .. DOUT*DIN-1
    int o = idx >> 10;          // / DIN
    int i = idx & (DIN - 1);    // % DIN
    float s1 = 0.f, s2 = 0.f;
#pragma unroll
    for (int r = 0; r < RANK; ++r) {
        s1 = fmaf(B1[o * RANK + r], A1[r * DIN + i], s1);
        s2 = fmaf(B2[o * RANK + r], A2[r * DIN + i], s2);
    }
    g_Weff[idx] = W[idx] + SCALE1 * s1 + SCALE2 * s2;
}

// out[t][o] = sum_i x[t][i] * W_eff[o][i] + b[o]
// 128x128 block tile, K-tile 16, 256 threads, 8x8 per-thread micro-tile.
__global__ __launch_bounds__(256)
void lora_gemm_kernel(const float* __restrict__ X,
                      const float* __restrict__ bias,
                      float* __restrict__ out) {
    // Transposed smem tiles: [k][row] so compute reads are broadcast / wide.
    __shared__ float As[16][128];  // x tile:   k x token-row
    __shared__ float Bs[16][128];  // W tile:   k x out-col

    const int tid = threadIdx.x;
    const int tx  = tid & 15;       // 0..15 -> output col group
    const int ty  = tid >> 4;       // 0..15 -> output row group
    const int row = tid >> 1;       // 0..127 (load row)
    const int kh  = (tid & 1) * 8;  // 0 or 8  (load k-half)

    const float* Xp = X      + (blockIdx.y * 128 + row) * DIN;
    const float* Wp = g_Weff + (blockIdx.x * 128 + row) * DIN;

    float acc[8][8];
#pragma unroll
    for (int i = 0; i < 8; ++i)
#pragma unroll
        for (int j = 0; j < 8; ++j) acc[i][j] = 0.f;

    for (int kt = 0; kt < DIN; kt += 16) {
        // Global loads (each thread: 8 floats of x, 8 floats of W)
        float4 xa = *reinterpret_cast<const float4*>(Xp + kt + kh);
        float4 xb = *reinterpret_cast<const float4*>(Xp + kt + kh + 4);
        float4 wa = *reinterpret_cast<const float4*>(Wp + kt + kh);
        float4 wb = *reinterpret_cast<const float4*>(Wp + kt + kh + 4);

        __syncthreads();  // previous tile's compute done before overwrite

        As[kh + 0][row] = xa.x; As[kh + 1][row] = xa.y;
        As[kh + 2][row] = xa.z; As[kh + 3][row] = xa.w;
        As[kh + 4][row] = xb.x; As[kh + 5][row] = xb.y;
        As[kh + 6][row] = xb.z; As[kh + 7][row] = xb.w;

        Bs[kh + 0][row] = wa.x; Bs[kh + 1][row] = wa.y;
        Bs[kh + 2][row] = wa.z; Bs[kh + 3][row] = wa.w;
        Bs[kh + 4][row] = wb.x; Bs[kh + 5][row] = wb.y;
        Bs[kh + 6][row] = wb.z; Bs[kh + 7][row] = wb.w;

        __syncthreads();

#pragma unroll
        for (int k = 0; k < 16; ++k) {
            float4 a0 = *reinterpret_cast<const float4*>(&As[k][ty * 8]);
            float4 a1 = *reinterpret_cast<const float4*>(&As[k][ty * 8 + 4]);
            float4 b0 = *reinterpret_cast<const float4*>(&Bs[k][tx * 8]);
            float4 b1 = *reinterpret_cast<const float4*>(&Bs[k][tx * 8 + 4]);
            float a[8] = {a0.x, a0.y, a0.z, a0.w, a1.x, a1.y, a1.z, a1.w};
            float b[8] = {b0.x, b0.y, b0.z, b0.w, b1.x, b1.y, b1.z, b1.w};
#pragma unroll
            for (int i = 0; i < 8; ++i)
#pragma unroll
                for (int j = 0; j < 8; ++j)
                    acc[i][j] = fmaf(a[i], b[j], acc[i][j]);
        }
    }

    // Epilogue: add bias, store (vectorized).
    const int orow = blockIdx.y * 128 + ty * 8;
    const int ocol = blockIdx.x * 128 + tx * 8;
    float4 bv0 = *reinterpret_cast<const float4*>(bias + ocol);
    float4 bv1 = *reinterpret_cast<const float4*>(bias + ocol + 4);
#pragma unroll
    for (int i = 0; i < 8; ++i) {
        float4 o0, o1;
        o0.x = acc[i][0] + bv0.x; o0.y = acc[i][1] + bv0.y;
        o0.z = acc[i][2] + bv0.z; o0.w = acc[i][3] + bv0.w;
        o1.x = acc[i][4] + bv1.x; o1.y = acc[i][5] + bv1.y;
        o1.z = acc[i][6] + bv1.z; o1.w = acc[i][7] + bv1.w;
        *reinterpret_cast<float4*>(out + (size_t)(orow + i) * DOUT + ocol)     = o0;
        *reinterpret_cast<float4*>(out + (size_t)(orow + i) * DOUT + ocol + 4) = o1;
    }
}

extern "C" void kernel_launch(void* const* d_in, const int* in_sizes, int n_in,
                              void* d_out, int out_size) {
    const float* x  = (const float*)d_in[0];
    const float* W  = (const float*)d_in[1];
    const float* b  = (const float*)d_in[2];
    const float* A1 = (const float*)d_in[3];
    const float* B1 = (const float*)d_in[4];
    const float* A2 = (const float*)d_in[5];
    const float* B2 = (const float*)d_in[6];
    float* out = (float*)d_out;

    build_weff_kernel<<<(DOUT * DIN) / 256, 256>>>(W, A1, B1, A2, B2);

    dim3 grid(DOUT / 128, TOKENS / 128);
    lora_gemm_kernel<<<grid, 256>>>(x, b, out);
}

// round 6
// speedup vs baseline: 2.8742x; 2.8742x over previous
#include <cuda_runtime.h>
#include <cuda_fp16.h>
#include <cstdint>

#define TOKENS 32768
#define DIN    1024
#define DOUT   1024
#define RANK   16

// ---------------- global scratch (device statics; no cudaMalloc) ----------------
__device__ __half g_xhi[(size_t)TOKENS * DIN];   // 64 MB
__device__ __half g_xlo[(size_t)TOKENS * DIN];   // 64 MB
__device__ __half g_whi[DOUT * DIN];             // 2 MB
__device__ __half g_wlo[DOUT * DIN];             // 2 MB

// ---------------- fold W + LoRA, split to fp16 hi/lo ----------------
__global__ __launch_bounds__(256)
void build_w_kernel(const float* __restrict__ W,
                    const float* __restrict__ A1, const float* __restrict__ B1,
                    const float* __restrict__ A2, const float* __restrict__ B2) {
    int idx = blockIdx.x * 256 + threadIdx.x;   // 0 .. DOUT*DIN-1
    int o = idx >> 10;
    int i = idx & 1023;
    float s1 = 0.f, s2 = 0.f;
#pragma unroll
    for (int r = 0; r < RANK; ++r) {
        s1 = fmaf(B1[o * RANK + r], A1[r * DIN + i], s1);
        s2 = fmaf(B2[o * RANK + r], A2[r * DIN + i], s2);
    }
    float w = W[idx] + 0.5f * s1 + s2;          // SCALE1=8/16, SCALE2=16/16
    __half hi = __float2half_rn(w);
    g_whi[idx] = hi;
    g_wlo[idx] = __float2half_rn(w - __half2float(hi));
}

// ---------------- split x into fp16 hi/lo ----------------
__global__ __launch_bounds__(256)
void split_x_kernel(const float* __restrict__ X) {
    size_t base = ((size_t)blockIdx.x * 256 + threadIdx.x) * 8;
    float4 v0 = *reinterpret_cast<const float4*>(X + base);
    float4 v1 = *reinterpret_cast<const float4*>(X + base + 4);
    float v[8] = {v0.x, v0.y, v0.z, v0.w, v1.x, v1.y, v1.z, v1.w};
    union { __half h[8]; uint4 q; } H, L;
#pragma unroll
    for (int j = 0; j < 8; ++j) {
        __half hi = __float2half_rn(v[j]);
        H.h[j] = hi;
        L.h[j] = __float2half_rn(v[j] - __half2float(hi));
    }
    *reinterpret_cast<uint4*>(g_xhi + base) = H.q;
    *reinterpret_cast<uint4*>(g_xlo + base) = L.q;
}

// ---------------- GEMM: out = x @ W_eff^T + b, 3-pass fp16 HMMA ----------------
#define BK      32                 // k-halves per stage
#define STAGES  3
#define STG     32768              // bytes per stage (4 tiles x 8KB)
#define XHI_OFF 0
#define XLO_OFF 8192
#define WHI_OFF 16384
#define WLO_OFF 24576
#define NKT     (DIN / BK)         // 32 k-tiles

__device__ __forceinline__ uint32_t smem_u32(const void* p) {
    uint32_t a;
    asm("{ .reg .u64 t; cvta.to.shared.u64 t, %1; cvt.u32.u64 %0, t; }" : "=r"(a) : "l"(p));
    return a;
}
__device__ __forceinline__ uint32_t swz64(uint32_t o) { return o ^ ((o >> 3) & 0x30); }

__device__ __forceinline__ void ldsm4(uint32_t* r, uint32_t addr) {
    asm volatile("ldmatrix.sync.aligned.m8n8.x4.shared.b16 {%0,%1,%2,%3}, [%4];"
        : "=r"(r[0]), "=r"(r[1]), "=r"(r[2]), "=r"(r[3]) : "r"(addr));
}
__device__ __forceinline__ void mma16816(float* c, const uint32_t* a, const uint32_t* b) {
    asm volatile("mma.sync.aligned.m16n8k16.row.col.f32.f16.f16.f32 "
        "{%0,%1,%2,%3}, {%4,%5,%6,%7}, {%8,%9}, {%0,%1,%2,%3};"
        : "+f"(c[0]), "+f"(c[1]), "+f"(c[2]), "+f"(c[3])
        : "r"(a[0]), "r"(a[1]), "r"(a[2]), "r"(a[3]), "r"(b[0]), "r"(b[1]));
}

#define CP16(dst, src) \
    asm volatile("cp.async.cg.shared.global [%0], [%1], 16;" :: "r"(dst), "l"(src))
#define CP_COMMIT() asm volatile("cp.async.commit_group;")
#define CP_WAIT1()  asm volatile("cp.async.wait_group 1;")

__global__ void __launch_bounds__(256, 2)
gemm_fp16x3(const float* __restrict__ bias, float* __restrict__ out) {
    extern __shared__ char sm[];
    const uint32_t sb = smem_u32(sm);
    const int tid  = threadIdx.x;
    const int lane = tid & 31;
    const int wid  = tid >> 5;
    const int wm   = wid & 3;        // 4 warp rows (32 m each)
    const int wn   = wid >> 2;       // 2 warp cols (64 n each)
    const int m0   = blockIdx.y * 128;
    const int n0   = blockIdx.x * 128;

    // cp.async mapping: thread -> (row = tid/4 and +64, 16B chunk col = tid%4)
    const int crow = tid >> 2;
    const int ccol = tid & 3;
    const __half* gxh = g_xhi + (size_t)(m0 + crow) * DIN + ccol * 8;
    const __half* gxl = g_xlo + (size_t)(m0 + crow) * DIN + ccol * 8;
    const __half* gwh = g_whi + (size_t)(n0 + crow) * DIN + ccol * 8;
    const __half* gwl = g_wlo + (size_t)(n0 + crow) * DIN + ccol * 8;
    const uint32_t sts0 = swz64((uint32_t)crow * 64 + (uint32_t)ccol * 16);

    // UNSWIZZLED ldmatrix lane offsets; swizzle applied per-(k-step) below.
    // (Fix for R5 fault: ks=32 touches swizzle bit 5, must be added pre-swizzle.)
    const uint32_t a_off = (uint32_t)(wm * 32 + (lane & 15)) * 64 + (uint32_t)(lane >> 4) * 16;
    const uint32_t b_off = (uint32_t)(wn * 64 + (lane >> 4) * 8 + (lane & 7)) * 64 +
                           (uint32_t)((lane >> 3) & 1) * 16;

    float acc[2][8][4];
#pragma unroll
    for (int mt = 0; mt < 2; ++mt)
#pragma unroll
        for (int nt = 0; nt < 8; ++nt)
#pragma unroll
            for (int c = 0; c < 4; ++c) acc[mt][nt][c] = 0.f;

    // ---- async copy of one k-tile into stage kt%STAGES ----
#define ISSUE(kt) do {                                                           \
        const uint32_t st_ = sb + ((kt) % STAGES) * STG;                         \
        const size_t go_ = (size_t)(kt) * BK;                                    \
        CP16(st_ + XHI_OFF + sts0,        gxh + go_);                            \
        CP16(st_ + XHI_OFF + sts0 + 4096, gxh + go_ + (size_t)64 * DIN);         \
        CP16(st_ + XLO_OFF + sts0,        gxl + go_);                            \
        CP16(st_ + XLO_OFF + sts0 + 4096, gxl + go_ + (size_t)64 * DIN);         \
        CP16(st_ + WHI_OFF + sts0,        gwh + go_);                            \
        CP16(st_ + WHI_OFF + sts0 + 4096, gwh + go_ + (size_t)64 * DIN);         \
        CP16(st_ + WLO_OFF + sts0,        gwl + go_);                            \
        CP16(st_ + WLO_OFF + sts0 + 4096, gwl + go_ + (size_t)64 * DIN);         \
    } while (0)

    ISSUE(0); CP_COMMIT();
    ISSUE(1); CP_COMMIT();

    for (int kt = 0; kt < NKT; ++kt) {
        CP_WAIT1();
        __syncthreads();

        if (kt + 2 < NKT) { ISSUE(kt + 2); }
        CP_COMMIT();

        const uint32_t st = sb + (kt % STAGES) * STG;
#pragma unroll
        for (int s = 0; s < 2; ++s) {
            const uint32_t ks = s * 32;
            const uint32_t a_sw = swz64(a_off + ks);   // pre-swizzle ks add (the fix)
            const uint32_t b_sw = swz64(b_off + ks);

            uint32_t bh[4][4];
#pragma unroll
            for (int j = 0; j < 4; ++j)
                ldsm4(bh[j], st + WHI_OFF + b_sw + j * 1024);

            uint32_t ah[2][4];
#pragma unroll
            for (int mt = 0; mt < 2; ++mt)
                ldsm4(ah[mt], st + XHI_OFF + a_sw + mt * 1024);

            // pass 1: xhi * whi
#pragma unroll
            for (int mt = 0; mt < 2; ++mt)
#pragma unroll
                for (int nt = 0; nt < 8; ++nt)
                    mma16816(acc[mt][nt], ah[mt], &bh[nt >> 1][(nt & 1) * 2]);

            uint32_t al[2][4];
#pragma unroll
            for (int mt = 0; mt < 2; ++mt)
                ldsm4(al[mt], st + XLO_OFF + a_sw + mt * 1024);

            // pass 2: xlo * whi
#pragma unroll
            for (int mt = 0; mt < 2; ++mt)
#pragma unroll
                for (int nt = 0; nt < 8; ++nt)
                    mma16816(acc[mt][nt], al[mt], &bh[nt >> 1][(nt & 1) * 2]);

            uint32_t bl[4][4];
#pragma unroll
            for (int j = 0; j < 4; ++j)
                ldsm4(bl[j], st + WLO_OFF + b_sw + j * 1024);

            // pass 3: xhi * wlo
#pragma unroll
            for (int mt = 0; mt < 2; ++mt)
#pragma unroll
                for (int nt = 0; nt < 8; ++nt)
                    mma16816(acc[mt][nt], ah[mt], &bl[nt >> 1][(nt & 1) * 2]);
        }
    }

    // ---- epilogue: add bias, store fp32 ----
    const int erow = m0 + wm * 32 + (lane >> 2);
    const int ecol = n0 + wn * 64 + (lane & 3) * 2;
#pragma unroll
    for (int nt = 0; nt < 8; ++nt) {
        const int c = ecol + nt * 8;
        const float b0 = bias[c], b1 = bias[c + 1];
#pragma unroll
        for (int mt = 0; mt < 2; ++mt) {
            const int r = erow + mt * 16;
            out[(size_t)r * DOUT + c]           = acc[mt][nt][0] + b0;
            out[(size_t)r * DOUT + c + 1]       = acc[mt][nt][1] + b1;
            out[(size_t)(r + 8) * DOUT + c]     = acc[mt][nt][2] + b0;
            out[(size_t)(r + 8) * DOUT + c + 1] = acc[mt][nt][3] + b1;
        }
    }
}

// ---------------- launch ----------------
extern "C" void kernel_launch(void* const* d_in, const int* in_sizes, int n_in,
                              void* d_out, int out_size) {
    const float* x  = (const float*)d_in[0];
    const float* W  = (const float*)d_in[1];
    const float* b  = (const float*)d_in[2];
    const float* A1 = (const float*)d_in[3];
    const float* B1 = (const float*)d_in[4];
    const float* A2 = (const float*)d_in[5];
    const float* B2 = (const float*)d_in[6];
    float* out = (float*)d_out;

    cudaFuncSetAttribute(gemm_fp16x3, cudaFuncAttributeMaxDynamicSharedMemorySize,
                         STAGES * STG);

    build_w_kernel<<<(DOUT * DIN) / 256, 256>>>(W, A1, B1, A2, B2);
    split_x_kernel<<<(int)(((size_t)TOKENS * DIN) / 8 / 256), 256>>>(x);

    dim3 grid(DOUT / 128, TOKENS / 128);   // (n-tiles, m-tiles)
    gemm_fp16x3<<<grid, 256, STAGES * STG>>>(b, out);
}

// round 8
// speedup vs baseline: 4.2089x; 1.4644x over previous
#include <cuda_runtime.h>
#include <cuda_fp16.h>
#include <cstdint>

#define TOKENS 32768
#define DIN    1024
#define DOUT   1024
#define RANK   16

// ---------------- global scratch (device statics; no cudaMalloc) ----------------
__device__ __half g_xhi[(size_t)TOKENS * DIN];   // 64 MB
__device__ __half g_whi[DOUT * DIN];             // 2 MB
__device__ __half g_wlo[DOUT * DIN];             // 2 MB

// ---------------- fold W + LoRA, split to fp16 hi/lo ----------------
__global__ __launch_bounds__(256)
void build_w_kernel(const float* __restrict__ W,
                    const float* __restrict__ A1, const float* __restrict__ B1,
                    const float* __restrict__ A2, const float* __restrict__ B2) {
    int idx = blockIdx.x * 256 + threadIdx.x;   // 0 .. DOUT*DIN-1
    int o = idx >> 10;
    int i = idx & 1023;
    float s1 = 0.f, s2 = 0.f;
#pragma unroll
    for (int r = 0; r < RANK; ++r) {
        s1 = fmaf(B1[o * RANK + r], A1[r * DIN + i], s1);
        s2 = fmaf(B2[o * RANK + r], A2[r * DIN + i], s2);
    }
    float w = W[idx] + 0.5f * s1 + s2;          // SCALE1=8/16, SCALE2=16/16
    __half hi = __float2half_rn(w);
    g_whi[idx] = hi;
    g_wlo[idx] = __float2half_rn(w - __half2float(hi));
}

// ---------------- convert x to fp16 (hi only) ----------------
__global__ __launch_bounds__(256)
void split_x_kernel(const float* __restrict__ X) {
    size_t base = ((size_t)blockIdx.x * 256 + threadIdx.x) * 8;
    float4 v0 = *reinterpret_cast<const float4*>(X + base);
    float4 v1 = *reinterpret_cast<const float4*>(X + base + 4);
    float v[8] = {v0.x, v0.y, v0.z, v0.w, v1.x, v1.y, v1.z, v1.w};
    union { __half h[8]; uint4 q; } H;
#pragma unroll
    for (int j = 0; j < 8; ++j) H.h[j] = __float2half_rn(v[j]);
    *reinterpret_cast<uint4*>(g_xhi + base) = H.q;
}

// ---------------- GEMM: out = x @ W_eff^T + b, 2-pass fp16 HMMA ----------------
// out ≈ xhi*whi + xhi*wlo  (xlo path dropped; error ~2e-4 vs 1e-3 budget)
#define BK      32                 // k-halves per stage
#define STAGES  4
#define STG     24576              // bytes per stage (3 tiles x 8KB)
#define XHI_OFF 0
#define WHI_OFF 8192
#define WLO_OFF 16384
#define NKT     (DIN / BK)         // 32 k-tiles

__device__ __forceinline__ uint32_t smem_u32(const void* p) {
    uint32_t a;
    asm("{ .reg .u64 t; cvta.to.shared.u64 t, %1; cvt.u32.u64 %0, t; }" : "=r"(a) : "l"(p));
    return a;
}
__device__ __forceinline__ uint32_t swz64(uint32_t o) { return o ^ ((o >> 3) & 0x30); }

__device__ __forceinline__ void ldsm4(uint32_t* r, uint32_t addr) {
    asm volatile("ldmatrix.sync.aligned.m8n8.x4.shared.b16 {%0,%1,%2,%3}, [%4];"
        : "=r"(r[0]), "=r"(r[1]), "=r"(r[2]), "=r"(r[3]) : "r"(addr));
}
__device__ __forceinline__ void mma16816(float* c, const uint32_t* a, const uint32_t* b) {
    asm volatile("mma.sync.aligned.m16n8k16.row.col.f32.f16.f16.f32 "
        "{%0,%1,%2,%3}, {%4,%5,%6,%7}, {%8,%9}, {%0,%1,%2,%3};"
        : "+f"(c[0]), "+f"(c[1]), "+f"(c[2]), "+f"(c[3])
        : "r"(a[0]), "r"(a[1]), "r"(a[2]), "r"(a[3]), "r"(b[0]), "r"(b[1]));
}

#define CP16(dst, src) \
    asm volatile("cp.async.cg.shared.global [%0], [%1], 16;" :: "r"(dst), "l"(src))
#define CP_COMMIT() asm volatile("cp.async.commit_group;")
#define CP_WAIT2()  asm volatile("cp.async.wait_group 2;")

__global__ void __launch_bounds__(256, 2)
gemm_fp16x2(const float* __restrict__ bias, float* __restrict__ out) {
    extern __shared__ char sm[];
    const uint32_t sb = smem_u32(sm);
    const int tid  = threadIdx.x;
    const int lane = tid & 31;
    const int wid  = tid >> 5;
    const int wm   = wid & 3;        // 4 warp rows (32 m each)
    const int wn   = wid >> 2;       // 2 warp cols (64 n each)
    const int m0   = blockIdx.y * 128;
    const int n0   = blockIdx.x * 128;

    // cp.async mapping: thread -> (rows tid/4 and +64, 16B chunk col = tid%4)
    const int crow = tid >> 2;
    const int ccol = tid & 3;
    const __half* gxh = g_xhi + (size_t)(m0 + crow) * DIN + ccol * 8;
    const __half* gwh = g_whi + (size_t)(n0 + crow) * DIN + ccol * 8;
    const __half* gwl = g_wlo + (size_t)(n0 + crow) * DIN + ccol * 8;
    const uint32_t sts0 = swz64((uint32_t)crow * 64 + (uint32_t)ccol * 16);

    // unswizzled ldmatrix lane offsets; swizzle applied after adding ks
    const uint32_t a_off = (uint32_t)(wm * 32 + (lane & 15)) * 64 + (uint32_t)(lane >> 4) * 16;
    const uint32_t b_off = (uint32_t)(wn * 64 + (lane >> 4) * 8 + (lane & 7)) * 64 +
                           (uint32_t)((lane >> 3) & 1) * 16;

    float acc[2][8][4];
#pragma unroll
    for (int mt = 0; mt < 2; ++mt)
#pragma unroll
        for (int nt = 0; nt < 8; ++nt)
#pragma unroll
            for (int c = 0; c < 4; ++c) acc[mt][nt][c] = 0.f;

#define ISSUE(kt) do {                                                           \
        const uint32_t st_ = sb + ((kt) % STAGES) * STG;                         \
        const size_t go_ = (size_t)(kt) * BK;                                    \
        CP16(st_ + XHI_OFF + sts0,        gxh + go_);                            \
        CP16(st_ + XHI_OFF + sts0 + 4096, gxh + go_ + (size_t)64 * DIN);         \
        CP16(st_ + WHI_OFF + sts0,        gwh + go_);                            \
        CP16(st_ + WHI_OFF + sts0 + 4096, gwh + go_ + (size_t)64 * DIN);         \
        CP16(st_ + WLO_OFF + sts0,        gwl + go_);                            \
        CP16(st_ + WLO_OFF + sts0 + 4096, gwl + go_ + (size_t)64 * DIN);         \
    } while (0)

    ISSUE(0); CP_COMMIT();
    ISSUE(1); CP_COMMIT();
    ISSUE(2); CP_COMMIT();

    for (int kt = 0; kt < NKT; ++kt) {
        CP_WAIT2();
        __syncthreads();

        if (kt + 3 < NKT) { ISSUE(kt + 3); }
        CP_COMMIT();

        const uint32_t st = sb + (kt % STAGES) * STG;
#pragma unroll
        for (int s = 0; s < 2; ++s) {
            const uint32_t ks = s * 32;
            const uint32_t a_sw = swz64(a_off + ks);
            const uint32_t b_sw = swz64(b_off + ks);

            uint32_t bh[4][4];
#pragma unroll
            for (int j = 0; j < 4; ++j)
                ldsm4(bh[j], st + WHI_OFF + b_sw + j * 1024);

            uint32_t ah[2][4];
#pragma unroll
            for (int mt = 0; mt < 2; ++mt)
                ldsm4(ah[mt], st + XHI_OFF + a_sw + mt * 1024);

            // pass 1: xhi * whi
#pragma unroll
            for (int mt = 0; mt < 2; ++mt)
#pragma unroll
                for (int nt = 0; nt < 8; ++nt)
                    mma16816(acc[mt][nt], ah[mt], &bh[nt >> 1][(nt & 1) * 2]);

            uint32_t bl[4][4];
#pragma unroll
            for (int j = 0; j < 4; ++j)
                ldsm4(bl[j], st + WLO_OFF + b_sw + j * 1024);

            // pass 2: xhi * wlo
#pragma unroll
            for (int mt = 0; mt < 2; ++mt)
#pragma unroll
                for (int nt = 0; nt < 8; ++nt)
                    mma16816(acc[mt][nt], ah[mt], &bl[nt >> 1][(nt & 1) * 2]);
        }
    }

    // ---- epilogue: add bias, store fp32 ----
    const int erow = m0 + wm * 32 + (lane >> 2);
    const int ecol = n0 + wn * 64 + (lane & 3) * 2;
#pragma unroll
    for (int nt = 0; nt < 8; ++nt) {
        const int c = ecol + nt * 8;
        const float b0 = bias[c], b1 = bias[c + 1];
#pragma unroll
        for (int mt = 0; mt < 2; ++mt) {
            const int r = erow + mt * 16;
            out[(size_t)r * DOUT + c]           = acc[mt][nt][0] + b0;
            out[(size_t)r * DOUT + c + 1]       = acc[mt][nt][1] + b1;
            out[(size_t)(r + 8) * DOUT + c]     = acc[mt][nt][2] + b0;
            out[(size_t)(r + 8) * DOUT + c + 1] = acc[mt][nt][3] + b1;
        }
    }
}

// ---------------- launch ----------------
extern "C" void kernel_launch(void* const* d_in, const int* in_sizes, int n_in,
                              void* d_out, int out_size) {
    const float* x  = (const float*)d_in[0];
    const float* W  = (const float*)d_in[1];
    const float* b  = (const float*)d_in[2];
    const float* A1 = (const float*)d_in[3];
    const float* B1 = (const float*)d_in[4];
    const float* A2 = (const float*)d_in[5];
    const float* B2 = (const float*)d_in[6];
    float* out = (float*)d_out;

    cudaFuncSetAttribute(gemm_fp16x2, cudaFuncAttributeMaxDynamicSharedMemorySize,
                         STAGES * STG);

    build_w_kernel<<<(DOUT * DIN) / 256, 256>>>(W, A1, B1, A2, B2);
    split_x_kernel<<<(int)(((size_t)TOKENS * DIN) / 8 / 256), 256>>>(x);

    dim3 grid(DOUT / 128, TOKENS / 128);   // (n-tiles, m-tiles)
    gemm_fp16x2<<<grid, 256, STAGES * STG>>>(b, out);
}

// round 9
// speedup vs baseline: 7.0604x; 1.6775x over previous
#include <cuda_runtime.h>
#include <cuda_fp16.h>
#include <cstdint>

#define TOKENS 32768
#define DIN    1024
#define DOUT   1024
#define RANK   16

// ---------------- global scratch (device statics; no cudaMalloc) ----------------
__device__ __half g_xhi[(size_t)TOKENS * DIN];   // 64 MB
__device__ __half g_whi[DOUT * DIN];             // 2 MB

// ---------------- fold W + LoRA, convert to fp16 ----------------
__global__ __launch_bounds__(256)
void build_w_kernel(const float* __restrict__ W,
                    const float* __restrict__ A1, const float* __restrict__ B1,
                    const float* __restrict__ A2, const float* __restrict__ B2) {
    int idx = blockIdx.x * 256 + threadIdx.x;   // 0 .. DOUT*DIN-1
    int o = idx >> 10;
    int i = idx & 1023;
    float s1 = 0.f, s2 = 0.f;
#pragma unroll
    for (int r = 0; r < RANK; ++r) {
        s1 = fmaf(B1[o * RANK + r], A1[r * DIN + i], s1);
        s2 = fmaf(B2[o * RANK + r], A2[r * DIN + i], s2);
    }
    float w = W[idx] + 0.5f * s1 + s2;          // SCALE1=8/16, SCALE2=16/16
    g_whi[idx] = __float2half_rn(w);
}

// ---------------- convert x to fp16 ----------------
__global__ __launch_bounds__(256)
void split_x_kernel(const float* __restrict__ X) {
    size_t base = ((size_t)blockIdx.x * 256 + threadIdx.x) * 8;
    float4 v0 = *reinterpret_cast<const float4*>(X + base);
    float4 v1 = *reinterpret_cast<const float4*>(X + base + 4);
    float v[8] = {v0.x, v0.y, v0.z, v0.w, v1.x, v1.y, v1.z, v1.w};
    union { __half h[8]; uint4 q; } H;
#pragma unroll
    for (int j = 0; j < 8; ++j) H.h[j] = __float2half_rn(v[j]);
    *reinterpret_cast<uint4*>(g_xhi + base) = H.q;
}

// ---------------- GEMM: out = xhi @ whi^T + b, single-pass fp16 HMMA ----------------
#define BK      32                 // k per stage
#define STAGES  4
#define STG     16384              // bytes per stage (2 tiles x 8KB)
#define XHI_OFF 0
#define WHI_OFF 8192
#define NKT     (DIN / BK)         // 32 k-tiles

__device__ __forceinline__ uint32_t smem_u32(const void* p) {
    uint32_t a;
    asm("{ .reg .u64 t; cvta.to.shared.u64 t, %1; cvt.u32.u64 %0, t; }" : "=r"(a) : "l"(p));
    return a;
}
__device__ __forceinline__ uint32_t swz64(uint32_t o) { return o ^ ((o >> 3) & 0x30); }

__device__ __forceinline__ void ldsm4(uint32_t* r, uint32_t addr) {
    asm volatile("ldmatrix.sync.aligned.m8n8.x4.shared.b16 {%0,%1,%2,%3}, [%4];"
        : "=r"(r[0]), "=r"(r[1]), "=r"(r[2]), "=r"(r[3]) : "r"(addr));
}
__device__ __forceinline__ void mma16816(float* c, const uint32_t* a, const uint32_t* b) {
    asm volatile("mma.sync.aligned.m16n8k16.row.col.f32.f16.f16.f32 "
        "{%0,%1,%2,%3}, {%4,%5,%6,%7}, {%8,%9}, {%0,%1,%2,%3};"
        : "+f"(c[0]), "+f"(c[1]), "+f"(c[2]), "+f"(c[3])
        : "r"(a[0]), "r"(a[1]), "r"(a[2]), "r"(a[3]), "r"(b[0]), "r"(b[1]));
}

#define CP16(dst, src) \
    asm volatile("cp.async.cg.shared.global [%0], [%1], 16;" :: "r"(dst), "l"(src))
#define CP_COMMIT() asm volatile("cp.async.commit_group;")
#define CP_WAIT2()  asm volatile("cp.async.wait_group 2;")

__global__ void __launch_bounds__(256, 2)
gemm_fp16x1(const float* __restrict__ bias, float* __restrict__ out) {
    extern __shared__ char sm[];
    const uint32_t sb = smem_u32(sm);
    const int tid  = threadIdx.x;
    const int lane = tid & 31;
    const int wid  = tid >> 5;
    const int wm   = wid & 3;        // 4 warp rows (32 m each)
    const int wn   = wid >> 2;       // 2 warp cols (64 n each)
    const int m0   = blockIdx.y * 128;
    const int n0   = blockIdx.x * 128;

    // cp.async mapping: thread -> (rows tid/4 and +64, 16B chunk col = tid%4)
    const int crow = tid >> 2;
    const int ccol = tid & 3;
    const __half* gxh = g_xhi + (size_t)(m0 + crow) * DIN + ccol * 8;
    const __half* gwh = g_whi + (size_t)(n0 + crow) * DIN + ccol * 8;
    const uint32_t sts0 = swz64((uint32_t)crow * 64 + (uint32_t)ccol * 16);

    // unswizzled ldmatrix lane offsets; swizzle applied after adding ks
    const uint32_t a_off = (uint32_t)(wm * 32 + (lane & 15)) * 64 + (uint32_t)(lane >> 4) * 16;
    const uint32_t b_off = (uint32_t)(wn * 64 + (lane >> 4) * 8 + (lane & 7)) * 64 +
                           (uint32_t)((lane >> 3) & 1) * 16;

    float acc[2][8][4];
#pragma unroll
    for (int mt = 0; mt < 2; ++mt)
#pragma unroll
        for (int nt = 0; nt < 8; ++nt)
#pragma unroll
            for (int c = 0; c < 4; ++c) acc[mt][nt][c] = 0.f;

#define ISSUE(kt) do {                                                           \
        const uint32_t st_ = sb + ((kt) % STAGES) * STG;                         \
        const size_t go_ = (size_t)(kt) * BK;                                    \
        CP16(st_ + XHI_OFF + sts0,        gxh + go_);                            \
        CP16(st_ + XHI_OFF + sts0 + 4096, gxh + go_ + (size_t)64 * DIN);         \
        CP16(st_ + WHI_OFF + sts0,        gwh + go_);                            \
        CP16(st_ + WHI_OFF + sts0 + 4096, gwh + go_ + (size_t)64 * DIN);         \
    } while (0)

    ISSUE(0); CP_COMMIT();
    ISSUE(1); CP_COMMIT();
    ISSUE(2); CP_COMMIT();

    for (int kt = 0; kt < NKT; ++kt) {
        CP_WAIT2();
        __syncthreads();

        if (kt + 3 < NKT) { ISSUE(kt + 3); }
        CP_COMMIT();

        const uint32_t st = sb + (kt % STAGES) * STG;
#pragma unroll
        for (int s = 0; s < 2; ++s) {
            const uint32_t ks = s * 32;
            const uint32_t a_sw = swz64(a_off + ks);
            const uint32_t b_sw = swz64(b_off + ks);

            uint32_t bh[4][4];
#pragma unroll
            for (int j = 0; j < 4; ++j)
                ldsm4(bh[j], st + WHI_OFF + b_sw + j * 1024);

            uint32_t ah[2][4];
#pragma unroll
            for (int mt = 0; mt < 2; ++mt)
                ldsm4(ah[mt], st + XHI_OFF + a_sw + mt * 1024);

#pragma unroll
            for (int mt = 0; mt < 2; ++mt)
#pragma unroll
                for (int nt = 0; nt < 8; ++nt)
                    mma16816(acc[mt][nt], ah[mt], &bh[nt >> 1][(nt & 1) * 2]);
        }
    }

    // ---- epilogue: add bias, store fp32 (float2) ----
    const int erow = m0 + wm * 32 + (lane >> 2);
    const int ecol = n0 + wn * 64 + (lane & 3) * 2;
#pragma unroll
    for (int nt = 0; nt < 8; ++nt) {
        const int c = ecol + nt * 8;
        const float b0 = bias[c], b1 = bias[c + 1];
#pragma unroll
        for (int mt = 0; mt < 2; ++mt) {
            const int r = erow + mt * 16;
            float2 o0 = make_float2(acc[mt][nt][0] + b0, acc[mt][nt][1] + b1);
            float2 o1 = make_float2(acc[mt][nt][2] + b0, acc[mt][nt][3] + b1);
            *reinterpret_cast<float2*>(out + (size_t)r * DOUT + c)       = o0;
            *reinterpret_cast<float2*>(out + (size_t)(r + 8) * DOUT + c) = o1;
        }
    }
}

// ---------------- launch ----------------
extern "C" void kernel_launch(void* const* d_in, const int* in_sizes, int n_in,
                              void* d_out, int out_size) {
    const float* x  = (const float*)d_in[0];
    const float* W  = (const float*)d_in[1];
    const float* b  = (const float*)d_in[2];
    const float* A1 = (const float*)d_in[3];
    const float* B1 = (const float*)d_in[4];
    const float* A2 = (const float*)d_in[5];
    const float* B2 = (const float*)d_in[6];
    float* out = (float*)d_out;

    cudaFuncSetAttribute(gemm_fp16x1, cudaFuncAttributeMaxDynamicSharedMemorySize,
                         STAGES * STG);

    build_w_kernel<<<(DOUT * DIN) / 256, 256>>>(W, A1, B1, A2, B2);
    split_x_kernel<<<(int)(((size_t)TOKENS * DIN) / 8 / 256), 256>>>(x);

    dim3 grid(DOUT / 128, TOKENS / 128);   // (n-tiles, m-tiles)
    gemm_fp16x1<<<grid, 256, STAGES * STG>>>(b, out);
}